// round 13
// baseline (speedup 1.0000x reference)
#include <cuda_runtime.h>
#include <cuda_bf16.h>
#include <cstdint>

#define HDIM 1024
#define BDIM 2048
#define SDIM 64
#define MROWS (BDIM * SDIM)   // 131072
#define NCHUNK 4
#define MCH   (MROWS / NCHUNK)          // 32768 rows / chunk
#define BCH   (BDIM / NCHUNK)           // 512 batches / chunk

// ---------------- scratch ----------------
__device__ __nv_bfloat16 g_abf [(size_t)MROWS * HDIM];
__device__ __nv_bfloat16 g_inbf[(size_t)BDIM * HDIM];
__device__ __nv_bfloat16 g_wqt [(size_t)HDIM * HDIM];
__device__ __nv_bfloat16 g_wkt [(size_t)HDIM * HDIM];
__device__ __nv_bfloat16 g_kc  [(size_t)MROWS * HDIM];
__device__ __nv_bfloat16 g_qpre[(size_t)BDIM * HDIM];
__device__ float         g_q   [(size_t)BDIM * HDIM];
__device__ float         g_beta[(size_t)BDIM * SDIM];

#define CPASYNC16(sm, gm) \
    asm volatile("cp.async.cg.shared.global [%0], [%1], 16;\n" :: "r"(sm), "l"(gm))
#define CP_COMMIT() asm volatile("cp.async.commit_group;\n" ::: "memory")
#define CP_WAIT1()  asm volatile("cp.async.wait_group 1;\n" ::: "memory")
#define CP_WAIT0()  asm volatile("cp.async.wait_group 0;\n" ::: "memory")
#define LDMX4(r0, r1, r2, r3, a) \
    asm volatile("ldmatrix.sync.aligned.m8n8.x4.shared.b16 {%0,%1,%2,%3}, [%4];" \
        : "=r"(r0), "=r"(r1), "=r"(r2), "=r"(r3) : "r"(a))

__device__ __forceinline__ uint32_t smem_u32(const void* p) {
    uint32_t a;
    asm("{ .reg .u64 t; cvta.to.shared.u64 t, %1; cvt.u32.u64 %0, t; }" : "=r"(a) : "l"(p));
    return a;
}

// ================= GEMM core (R4 config, as device function) =================
#define NSTG   3
#define KC     64
#define CHUNKS (HDIM / KC)              // 16
#define RSTRIDE 144
#define STG_A   (128 * RSTRIDE)
#define STG_BYTES (2 * STG_A)           // 36864
#define GEMM_SMEM (NSTG * STG_BYTES)    // 110592

__device__ __forceinline__ void gemm_core(
    char* smem, uint32_t sb,
    const __nv_bfloat16* __restrict__ A, const __nv_bfloat16* __restrict__ Bt,
    __nv_bfloat16* __restrict__ C, size_t bm, size_t bn)
{
    const int tid   = threadIdx.x;
    const int lane  = tid & 31;
    const int wid   = tid >> 5;
    const int warpM = wid >> 2;
    const int warpN = wid & 3;

    float acc[4][4][4];
    #pragma unroll
    for (int mt = 0; mt < 4; mt++)
        #pragma unroll
        for (int nt = 0; nt < 4; nt++)
            #pragma unroll
            for (int i = 0; i < 4; i++) acc[mt][nt][i] = 0.f;

    const int prow = tid >> 3;
    const int pg   = tid & 7;
    const __nv_bfloat16* gA = A  + (bm + prow) * HDIM + pg * 8;
    const __nv_bfloat16* gB = Bt + (bn + prow) * HDIM + pg * 8;
    const uint32_t pdst = prow * RSTRIDE + pg * 16;

    const uint32_t aF = (warpM * 64 + ((lane >> 3) & 1) * 8 + (lane & 7)) * RSTRIDE
                      + ((lane >> 4) * 8) * 2;
    const uint32_t bF = STG_A
                      + (warpN * 32 + ((lane >> 4) & 1) * 8 + (lane & 7)) * RSTRIDE
                      + (((lane >> 3) & 1) * 8) * 2;

    #pragma unroll
    for (int kt = 0; kt < 2; kt++) {
        const uint32_t s = sb + kt * STG_BYTES;
        #pragma unroll
        for (int i = 0; i < 4; i++) {
            CPASYNC16(s + pdst + i * 32 * RSTRIDE,          gA + (size_t)i * 32 * HDIM + kt * KC);
            CPASYNC16(s + STG_A + pdst + i * 32 * RSTRIDE,  gB + (size_t)i * 32 * HDIM + kt * KC);
        }
        CP_COMMIT();
    }

    for (int kt = 0; kt < CHUNKS; kt++) {
        if (kt < CHUNKS - 1) CP_WAIT1(); else CP_WAIT0();
        __syncthreads();

        if (kt + 2 < CHUNKS) {
            const uint32_t s = sb + ((kt + 2) % NSTG) * STG_BYTES;
            #pragma unroll
            for (int i = 0; i < 4; i++) {
                CPASYNC16(s + pdst + i * 32 * RSTRIDE,         gA + (size_t)i * 32 * HDIM + (kt + 2) * KC);
                CPASYNC16(s + STG_A + pdst + i * 32 * RSTRIDE, gB + (size_t)i * 32 * HDIM + (kt + 2) * KC);
            }
            CP_COMMIT();
        }

        const uint32_t stg = sb + (kt % NSTG) * STG_BYTES;
        #pragma unroll
        for (int ks = 0; ks < KC; ks += 16) {
            uint32_t af[4][4];
            uint32_t bf[4][2];
            #pragma unroll
            for (int mt = 0; mt < 4; mt++)
                LDMX4(af[mt][0], af[mt][1], af[mt][2], af[mt][3],
                      stg + aF + mt * 16 * RSTRIDE + ks * 2);
            #pragma unroll
            for (int np = 0; np < 2; np++) {
                uint32_t b0, b1, b2, b3;
                LDMX4(b0, b1, b2, b3, stg + bF + np * 16 * RSTRIDE + ks * 2);
                bf[2*np][0]   = b0; bf[2*np][1]   = b1;
                bf[2*np+1][0] = b2; bf[2*np+1][1] = b3;
            }
            #pragma unroll
            for (int mt = 0; mt < 4; mt++)
                #pragma unroll
                for (int nt = 0; nt < 4; nt++)
                    asm volatile(
                        "mma.sync.aligned.m16n8k16.row.col.f32.bf16.bf16.f32 "
                        "{%0,%1,%2,%3},{%4,%5,%6,%7},{%8,%9},{%0,%1,%2,%3};\n"
                        : "+f"(acc[mt][nt][0]), "+f"(acc[mt][nt][1]),
                          "+f"(acc[mt][nt][2]), "+f"(acc[mt][nt][3])
                        : "r"(af[mt][0]), "r"(af[mt][1]), "r"(af[mt][2]), "r"(af[mt][3]),
                          "r"(bf[nt][0]), "r"(bf[nt][1]));
        }
    }

    #pragma unroll
    for (int mt = 0; mt < 4; mt++) {
        int r = warpM * 64 + mt * 16 + (lane >> 2);
        #pragma unroll
        for (int nt = 0; nt < 4; nt++) {
            size_t c  = bn + warpN * 32 + nt * 8 + (lane & 3) * 2;
            size_t b0 = (bm + r) * HDIM + c;
            *(__nv_bfloat162*)(C + b0) =
                __floats2bfloat162_rn(acc[mt][nt][0], acc[mt][nt][1]);
            *(__nv_bfloat162*)(C + b0 + (size_t)8 * HDIM) =
                __floats2bfloat162_rn(acc[mt][nt][2], acc[mt][nt][3]);
        }
    }
}

// ---------------- cvt role: 32768 elems / block, 16 iters ----------------
__device__ __forceinline__ void cvt_role(const float* __restrict__ in,
                                         __nv_bfloat16* __restrict__ out, int id)
{
    size_t base = (size_t)id * 32768 + threadIdx.x * 8;
    #pragma unroll
    for (int it = 0; it < 16; it++) {
        size_t i = base + (size_t)it * 2048;
        float4 a = *(const float4*)(in + i);
        float4 b = *(const float4*)(in + i + 4);
        __nv_bfloat162 r[4];
        r[0] = __floats2bfloat162_rn(a.x, a.y);
        r[1] = __floats2bfloat162_rn(a.z, a.w);
        r[2] = __floats2bfloat162_rn(b.x, b.y);
        r[3] = __floats2bfloat162_rn(b.z, b.w);
        *(uint4*)(out + i) = *(const uint4*)r;
    }
}

// ---------------- beta role (smem carved from dynamic buffer) ----------------
__device__ __forceinline__ void beta_role(
    char* smem,
    const __nv_bfloat16* __restrict__ kc, const float* __restrict__ q,
    const float* __restrict__ bk, const float* __restrict__ gk,
    const float* __restrict__ betak, const float* __restrict__ Wb,
    const float* __restrict__ bb, float* __restrict__ beta, int b)
{
    float* bks = (float*)smem;
    float* gks = bks + HDIM;
    float* cqs = gks + HDIM;
    float* wbs = cqs + HDIM;
    __nv_bfloat16* rowbuf = (__nv_bfloat16*)(smem + 4 * HDIM * 4);

    const int tid  = threadIdx.x;
    const int lane = tid & 31;
    const int wid  = tid >> 5;

    for (int j = tid; j < HDIM; j += 256) {
        bks[j] = bk[j];
        gks[j] = gk[j];
        cqs[j] = betak[j] + q[(size_t)b * HDIM + j];
        wbs[j] = Wb[j];
    }
    __syncthreads();
    const float bbv = bb[0];

    __nv_bfloat16* mybuf = rowbuf + wid * 2 * HDIM;
    const uint32_t buf_s = smem_u32(mybuf);
    const __nv_bfloat16* gbase = kc + ((size_t)b * SDIM) * HDIM;

    {
        const __nv_bfloat16* src = gbase + (size_t)wid * HDIM;
        #pragma unroll
        for (int qd = 0; qd < 4; qd++)
            CPASYNC16(buf_s + qd * 512 + lane * 16, src + qd * 256 + lane * 8);
        CP_COMMIT();
    }

    #pragma unroll
    for (int i = 0; i < 8; i++) {
        const int s = wid + i * 8;
        if (i < 7) {
            const __nv_bfloat16* src = gbase + (size_t)(s + 8) * HDIM;
            const uint32_t d = buf_s + ((i + 1) & 1) * (HDIM * 2);
            #pragma unroll
            for (int qd = 0; qd < 4; qd++)
                CPASYNC16(d + qd * 512 + lane * 16, src + qd * 256 + lane * 8);
            CP_COMMIT();
            CP_WAIT1();
        } else {
            CP_WAIT0();
        }
        __syncwarp();

        const __nv_bfloat16* rb = mybuf + (i & 1) * HDIM;
        float x[32];
        float sm = 0.f, sq = 0.f;
        #pragma unroll
        for (int it = 0; it < 4; it++) {
            int j0 = it * 256 + lane * 8;
            uint4 raw = *(const uint4*)(rb + j0);
            const __nv_bfloat162* v2 = (const __nv_bfloat162*)&raw;
            #pragma unroll
            for (int e = 0; e < 4; e++) {
                float a = __low2float(v2[e])  + bks[j0 + 2*e];
                float c = __high2float(v2[e]) + bks[j0 + 2*e + 1];
                x[it*8 + 2*e]     = a;
                x[it*8 + 2*e + 1] = c;
                sm += a + c; sq += a * a + c * c;
            }
        }
        __syncwarp();
        #pragma unroll
        for (int o = 16; o > 0; o >>= 1) {
            sm += __shfl_xor_sync(0xffffffffu, sm, o);
            sq += __shfl_xor_sync(0xffffffffu, sq, o);
        }
        float mean = sm * (1.f / 1024.f);
        float var  = sq * (1.f / 1024.f) - mean * mean;
        float rstd = rsqrtf(var + 1e-5f);

        float acc = 0.f;
        #pragma unroll
        for (int it = 0; it < 4; it++) {
            int j0 = it * 256 + lane * 8;
            #pragma unroll
            for (int e = 0; e < 8; e++) {
                float hv = (x[it*8 + e] - mean) * rstd * gks[j0 + e] + cqs[j0 + e];
                acc += fmaxf(hv, 0.f) * wbs[j0 + e];
            }
        }
        #pragma unroll
        for (int o = 16; o > 0; o >>= 1)
            acc += __shfl_xor_sync(0xffffffffu, acc, o);

        if (lane == 0)
            beta[(size_t)b * SDIM + s] = (acc + bbv) * (1.f / 32.f);
    }
}

// ================= mega kernel: role-striped grid =================
// head: nq q-GEMM blocks. Then stripes of (pg GEMM, pc cvt, pb beta).
__global__ __launch_bounds__(256, 2) void mega_k(
    int nq, int pg, int pc, int pb,
    const __nv_bfloat16* A, const __nv_bfloat16* WkT, __nv_bfloat16* C,
    const __nv_bfloat16* Aq, const __nv_bfloat16* WqT, __nv_bfloat16* Cq,
    const float* cvt_src, __nv_bfloat16* cvt_dst,
    const __nv_bfloat16* bkc, const float* qf, float* bout,
    const float* bk, const float* gk, const float* betak,
    const float* Wb, const float* bb)
{
    extern __shared__ __align__(128) char smem[];
    const uint32_t sb = smem_u32(smem);

    int bid = blockIdx.y * gridDim.x + blockIdx.x;
    if (bid < nq) {
        gemm_core(smem, sb, Aq, WqT, Cq, (size_t)(bid >> 3) * 128, (size_t)(bid & 7) * 128);
        return;
    }
    bid -= nq;
    const int P = pg + pc + pb;
    const int grp = bid / P;
    const int r   = bid % P;
    if (r < pg) {
        int id = grp * pg + r;
        gemm_core(smem, sb, A, WkT, C, (size_t)(id >> 3) * 128, (size_t)(id & 7) * 128);
    } else if (r < pg + pc) {
        int id = grp * pc + (r - pg);
        cvt_role(cvt_src, cvt_dst, id);
    } else {
        int id = grp * pb + (r - pg - pc);
        beta_role(smem, bkc, qf, bk, gk, betak, Wb, bb, bout, id);
    }
}

// ---------------- standalone kernels ----------------
__global__ __launch_bounds__(256) void cvt_k(const float* __restrict__ in,
                                             __nv_bfloat16* __restrict__ out)
{
    size_t i = ((size_t)blockIdx.x * blockDim.x + threadIdx.x) * 8;
    float4 a = *(const float4*)(in + i);
    float4 b = *(const float4*)(in + i + 4);
    __nv_bfloat162 r[4];
    r[0] = __floats2bfloat162_rn(a.x, a.y);
    r[1] = __floats2bfloat162_rn(a.z, a.w);
    r[2] = __floats2bfloat162_rn(b.x, b.y);
    r[3] = __floats2bfloat162_rn(b.z, b.w);
    *(uint4*)(out + i) = *(const uint4*)r;
}

__global__ __launch_bounds__(256) void cvtT_k(const float* __restrict__ W,
                                              __nv_bfloat16* __restrict__ Wt)
{
    __shared__ float t[32][33];
    int x  = blockIdx.x * 32 + threadIdx.x;
    int y0 = blockIdx.y * 32;
    #pragma unroll
    for (int r = threadIdx.y; r < 32; r += 8)
        t[r][threadIdx.x] = W[(size_t)(y0 + r) * HDIM + x];
    __syncthreads();
    int xo = y0 + threadIdx.x;
    #pragma unroll
    for (int r = threadIdx.y; r < 32; r += 8)
        Wt[(size_t)(blockIdx.x * 32 + r) * HDIM + xo] = __float2bfloat16(t[threadIdx.x][r]);
}

__global__ __launch_bounds__(256) void ln_q_k(
    const __nv_bfloat16* __restrict__ qpre,
    const float* __restrict__ bq, const float* __restrict__ gq,
    const float* __restrict__ betaq, float* __restrict__ qout)
{
    const int lane = threadIdx.x & 31;
    const int wid  = threadIdx.x >> 5;
    const int row  = blockIdx.x * 8 + wid;
    const size_t base = (size_t)row * HDIM;

    float x[32];
    float s = 0.f, sq = 0.f;
    #pragma unroll
    for (int i = 0; i < 16; i++) {
        int j = i * 64 + lane * 2;
        __nv_bfloat162 v = *(const __nv_bfloat162*)(qpre + base + j);
        float a = __low2float(v)  + bq[j];
        float c = __high2float(v) + bq[j + 1];
        x[2*i] = a; x[2*i+1] = c;
        s += a + c; sq += a * a + c * c;
    }
    #pragma unroll
    for (int o = 16; o > 0; o >>= 1) {
        s  += __shfl_xor_sync(0xffffffffu, s,  o);
        sq += __shfl_xor_sync(0xffffffffu, sq, o);
    }
    float mean = s * (1.f / 1024.f);
    float var  = sq * (1.f / 1024.f) - mean * mean;
    float rstd = rsqrtf(var + 1e-5f);
    #pragma unroll
    for (int i = 0; i < 16; i++) {
        int j = i * 64 + lane * 2;
        float2 o;
        o.x = (x[2*i]   - mean) * rstd * gq[j]   + betaq[j];
        o.y = (x[2*i+1] - mean) * rstd * gq[j+1] + betaq[j+1];
        *(float2*)(qout + base + j) = o;
    }
}

// standalone beta (chunk 3 tail) — same body via dynamic smem
__global__ __launch_bounds__(256) void beta_k(
    const __nv_bfloat16* __restrict__ kc, const float* __restrict__ q,
    const float* __restrict__ bk, const float* __restrict__ gk,
    const float* __restrict__ betak, const float* __restrict__ Wb,
    const float* __restrict__ bb, float* __restrict__ beta)
{
    extern __shared__ __align__(128) char smem[];
    beta_role(smem, kc, q, bk, gk, betak, Wb, bb, beta, blockIdx.x);
}
#define BETA_SMEM (4 * HDIM * 4 + 8 * 2 * HDIM * 2)   // 16KB + 32KB = 49152

__global__ void softmax_k(const float* __restrict__ beta,
                          const float* __restrict__ prev_p,
                          float* __restrict__ out)
{
    int b = blockIdx.x * blockDim.x + threadIdx.x;
    if (b >= BDIM) return;
    const float* bt = beta   + (size_t)b * SDIM;
    const float* pp = prev_p + (size_t)b * SDIM;

    float mx = -1e30f;
    #pragma unroll
    for (int s = 0; s < SDIM; s++) mx = fmaxf(mx, bt[s]);

    float pcs[SDIM];
    float run = 0.f;
    #pragma unroll
    for (int s = 0; s < SDIM; s++) { run += pp[s]; pcs[s] = run; }

    float x[SDIM];
    float denom = 0.f;
    #pragma unroll
    for (int s = 0; s < SDIM; s++) {
        float mask = (s < SDIM - 1)
                   ? ((pcs[s + 1] < 1e-5f) ? 0.f : pcs[s + 1])
                   : 1.f;
        x[s] = expf(bt[s] - mx) * mask;
        denom += fabsf(x[s]);
    }
    denom = fmaxf(denom, 1e-12f);

    const size_t BS = (size_t)BDIM * SDIM;
    float cp = 0.f;
    #pragma unroll
    for (int s = 0; s < SDIM; s++) {
        float p = x[s] / denom;
        x[s] = p;
        cp += p;
        out[0 * BS + (size_t)b * SDIM + s] = cp;
        out[2 * BS + (size_t)b * SDIM + s] = p;
    }
    float rcp = 0.f;
    #pragma unroll
    for (int s = SDIM - 1; s >= 0; s--) {
        rcp += x[s];
        out[1 * BS + (size_t)b * SDIM + s] = rcp;
    }
}

// ---------------- launch: single stream, role-packed launches ----------------
extern "C" void kernel_launch(void* const* d_in, const int* in_sizes, int n_in,
                              void* d_out, int out_size)
{
    const float* in_val     = (const float*)d_in[0];
    const float* prev_out_M = (const float*)d_in[1];
    const float* prev_p     = (const float*)d_in[2];
    const float* Wq         = (const float*)d_in[3];
    const float* bq         = (const float*)d_in[4];
    const float* gq         = (const float*)d_in[5];
    const float* betaq      = (const float*)d_in[6];
    const float* Wk         = (const float*)d_in[7];
    const float* bk         = (const float*)d_in[8];
    const float* gk         = (const float*)d_in[9];
    const float* betak      = (const float*)d_in[10];
    const float* Wb         = (const float*)d_in[11];
    const float* bb         = (const float*)d_in[12];
    float* out = (float*)d_out;

    __nv_bfloat16 *abf, *inbf, *wqt, *wkt, *kc, *qpre;
    float *qf, *betap;
    cudaGetSymbolAddress((void**)&abf,   g_abf);
    cudaGetSymbolAddress((void**)&inbf,  g_inbf);
    cudaGetSymbolAddress((void**)&wqt,   g_wqt);
    cudaGetSymbolAddress((void**)&wkt,   g_wkt);
    cudaGetSymbolAddress((void**)&kc,    g_kc);
    cudaGetSymbolAddress((void**)&qpre,  g_qpre);
    cudaGetSymbolAddress((void**)&qf,    g_q);
    cudaGetSymbolAddress((void**)&betap, g_beta);

    cudaFuncSetAttribute(mega_k, cudaFuncAttributeMaxDynamicSharedMemorySize, GEMM_SMEM);
    cudaFuncSetAttribute(beta_k, cudaFuncAttributeMaxDynamicSharedMemorySize, BETA_SMEM);

    const size_t CHW = (size_t)MCH * HDIM;   // elems per chunk

    // prologue: weights, in_val, chunk0 cvt
    cvtT_k<<<dim3(32, 32), dim3(32, 8)>>>(Wq, wqt);
    cvtT_k<<<dim3(32, 32), dim3(32, 8)>>>(Wk, wkt);
    cvt_k <<<((size_t)BDIM * HDIM / 8) / 256, 256>>>(in_val, inbf);
    cvt_k <<<(CHW / 8) / 256, 256>>>(prev_out_M, abf);

    // L1: GEMM chunk0 + qGEMM (head) + cvt chunk1.  2048 g, 1024 c -> stripe (2,1,0)
    mega_k<<<dim3(8, 400), 256, GEMM_SMEM>>>(
        128, 2, 1, 0,
        abf, wkt, kc,
        inbf, wqt, qpre,
        prev_out_M + CHW, abf + CHW,
        nullptr, nullptr, nullptr,
        bk, gk, betak, Wb, bb);

    ln_q_k<<<BDIM / 8, 256>>>(qpre, bq, gq, betaq, qf);

    // L2: GEMM chunk1 + cvt chunk2 + beta chunk0.  stripe (4,2,1)
    mega_k<<<dim3(8, 448), 256, GEMM_SMEM>>>(
        0, 4, 2, 1,
        abf + CHW, wkt, kc + CHW,
        nullptr, nullptr, nullptr,
        prev_out_M + 2 * CHW, abf + 2 * CHW,
        kc, qf, betap,
        bk, gk, betak, Wb, bb);

    // L3: GEMM chunk2 + cvt chunk3 + beta chunk1
    mega_k<<<dim3(8, 448), 256, GEMM_SMEM>>>(
        0, 4, 2, 1,
        abf + 2 * CHW, wkt, kc + 2 * CHW,
        nullptr, nullptr, nullptr,
        prev_out_M + 3 * CHW, abf + 3 * CHW,
        kc + CHW, qf + (size_t)BCH * HDIM, betap + (size_t)BCH * SDIM,
        bk, gk, betak, Wb, bb);

    // L4: GEMM chunk3 + beta chunk2.  stripe (4,0,1)
    mega_k<<<dim3(8, 320), 256, GEMM_SMEM>>>(
        0, 4, 0, 1,
        abf + 3 * CHW, wkt, kc + 3 * CHW,
        nullptr, nullptr, nullptr,
        nullptr, nullptr,
        kc + 2 * CHW, qf + (size_t)2 * BCH * HDIM, betap + (size_t)2 * BCH * SDIM,
        bk, gk, betak, Wb, bb);

    // tail: beta chunk3, softmax
    beta_k<<<BCH, 256, BETA_SMEM>>>(
        kc + 3 * CHW, qf + (size_t)3 * BCH * HDIM,
        bk, gk, betak, Wb, bb, betap + (size_t)3 * BCH * SDIM);
    softmax_k<<<(BDIM + 127) / 128, 128>>>(betap, prev_p, out);
}

// round 16
// speedup vs baseline: 1.0081x; 1.0081x over previous
#include <cuda_runtime.h>
#include <cuda_bf16.h>
#include <cstdint>

#define HDIM 1024
#define BDIM 2048
#define SDIM 64
#define MROWS (BDIM * SDIM)   // 131072

// ---------------- scratch ----------------
__device__ __nv_bfloat16 g_abf [(size_t)MROWS * HDIM];
__device__ __nv_bfloat16 g_inbf[(size_t)BDIM * HDIM];
__device__ __nv_bfloat16 g_wqt [(size_t)HDIM * HDIM];
__device__ __nv_bfloat16 g_wkt [(size_t)HDIM * HDIM];
__device__ __nv_bfloat16 g_kc  [(size_t)MROWS * HDIM];
__device__ __nv_bfloat16 g_qpre[(size_t)BDIM * HDIM];
__device__ float         g_beta[(size_t)BDIM * SDIM];

#define CPASYNC16(sm, gm) \
    asm volatile("cp.async.cg.shared.global [%0], [%1], 16;\n" :: "r"(sm), "l"(gm))
#define CP_COMMIT() asm volatile("cp.async.commit_group;\n" ::: "memory")
#define CP_WAIT1()  asm volatile("cp.async.wait_group 1;\n" ::: "memory")
#define CP_WAIT0()  asm volatile("cp.async.wait_group 0;\n" ::: "memory")
#define LDMX4(r0, r1, r2, r3, a) \
    asm volatile("ldmatrix.sync.aligned.m8n8.x4.shared.b16 {%0,%1,%2,%3}, [%4];" \
        : "=r"(r0), "=r"(r1), "=r"(r2), "=r"(r3) : "r"(a))

__device__ __forceinline__ uint32_t smem_u32(const void* p) {
    uint32_t a;
    asm("{ .reg .u64 t; cvta.to.shared.u64 t, %1; cvt.u32.u64 %0, t; }" : "=r"(a) : "l"(p));
    return a;
}

// ================= pipelined bf16 mma.sync GEMM (R4 core + staged epilogue) =================
// blockIdx.y < 16  -> query GEMM; else key GEMM. CTA 128x128, KC=64, 3-stage, 2 CTA/SM.
#define NSTG   3
#define KC     64
#define CHUNKS (HDIM / KC)              // 16
#define RSTRIDE 144
#define STG_A   (128 * RSTRIDE)
#define STG_BYTES (2 * STG_A)           // 36864
#define GEMM_SMEM (NSTG * STG_BYTES)    // 110592
#define ESTRIDE 272                     // epilogue smem row stride (17*16 B, 16B-aligned rows)

#define QBLKS (BDIM / 128)              // 16

__global__ __launch_bounds__(256, 2) void gemm_bf16_k(
    const __nv_bfloat16* __restrict__ A0, const __nv_bfloat16* __restrict__ Bt0,
    __nv_bfloat16* __restrict__ C0,
    const __nv_bfloat16* __restrict__ A1, const __nv_bfloat16* __restrict__ Bt1,
    __nv_bfloat16* __restrict__ C1)
{
    extern __shared__ __align__(128) char smem[];
    const uint32_t sb = smem_u32(smem);

    const int tid   = threadIdx.x;
    const int lane  = tid & 31;
    const int wid   = tid >> 5;
    const int warpM = wid >> 2;
    const int warpN = wid & 3;

    const bool small = (blockIdx.y < QBLKS);
    const __nv_bfloat16* A  = small ? A0  : A1;
    const __nv_bfloat16* Bt = small ? Bt0 : Bt1;
    __nv_bfloat16*       C  = small ? C0  : C1;
    const size_t bm = (size_t)(small ? blockIdx.y : (blockIdx.y - QBLKS)) * 128;
    const size_t bn = (size_t)blockIdx.x * 128;

    float acc[4][4][4];
    #pragma unroll
    for (int mt = 0; mt < 4; mt++)
        #pragma unroll
        for (int nt = 0; nt < 4; nt++)
            #pragma unroll
            for (int i = 0; i < 4; i++) acc[mt][nt][i] = 0.f;

    const int prow = tid >> 3;
    const int pg   = tid & 7;
    const __nv_bfloat16* gA = A  + (bm + prow) * HDIM + pg * 8;
    const __nv_bfloat16* gB = Bt + (bn + prow) * HDIM + pg * 8;
    const uint32_t pdst = prow * RSTRIDE + pg * 16;

    const uint32_t aF = (warpM * 64 + ((lane >> 3) & 1) * 8 + (lane & 7)) * RSTRIDE
                      + ((lane >> 4) * 8) * 2;
    const uint32_t bF = STG_A
                      + (warpN * 32 + ((lane >> 4) & 1) * 8 + (lane & 7)) * RSTRIDE
                      + (((lane >> 3) & 1) * 8) * 2;

    #pragma unroll
    for (int kt = 0; kt < 2; kt++) {
        const uint32_t s = sb + kt * STG_BYTES;
        #pragma unroll
        for (int i = 0; i < 4; i++) {
            CPASYNC16(s + pdst + i * 32 * RSTRIDE,          gA + (size_t)i * 32 * HDIM + kt * KC);
            CPASYNC16(s + STG_A + pdst + i * 32 * RSTRIDE,  gB + (size_t)i * 32 * HDIM + kt * KC);
        }
        CP_COMMIT();
    }

    for (int kt = 0; kt < CHUNKS; kt++) {
        if (kt < CHUNKS - 1) CP_WAIT1(); else CP_WAIT0();
        __syncthreads();

        if (kt + 2 < CHUNKS) {
            const uint32_t s = sb + ((kt + 2) % NSTG) * STG_BYTES;
            #pragma unroll
            for (int i = 0; i < 4; i++) {
                CPASYNC16(s + pdst + i * 32 * RSTRIDE,         gA + (size_t)i * 32 * HDIM + (kt + 2) * KC);
                CPASYNC16(s + STG_A + pdst + i * 32 * RSTRIDE, gB + (size_t)i * 32 * HDIM + (kt + 2) * KC);
            }
            CP_COMMIT();
        }

        const uint32_t stg = sb + (kt % NSTG) * STG_BYTES;
        #pragma unroll
        for (int ks = 0; ks < KC; ks += 16) {
            uint32_t af[4][4];
            uint32_t bf[4][2];
            #pragma unroll
            for (int mt = 0; mt < 4; mt++)
                LDMX4(af[mt][0], af[mt][1], af[mt][2], af[mt][3],
                      stg + aF + mt * 16 * RSTRIDE + ks * 2);
            #pragma unroll
            for (int np = 0; np < 2; np++) {
                uint32_t b0, b1, b2, b3;
                LDMX4(b0, b1, b2, b3, stg + bF + np * 16 * RSTRIDE + ks * 2);
                bf[2*np][0]   = b0; bf[2*np][1]   = b1;
                bf[2*np+1][0] = b2; bf[2*np+1][1] = b3;
            }
            #pragma unroll
            for (int mt = 0; mt < 4; mt++)
                #pragma unroll
                for (int nt = 0; nt < 4; nt++)
                    asm volatile(
                        "mma.sync.aligned.m16n8k16.row.col.f32.bf16.bf16.f32 "
                        "{%0,%1,%2,%3},{%4,%5,%6,%7},{%8,%9},{%0,%1,%2,%3};\n"
                        : "+f"(acc[mt][nt][0]), "+f"(acc[mt][nt][1]),
                          "+f"(acc[mt][nt][2]), "+f"(acc[mt][nt][3])
                        : "r"(af[mt][0]), "r"(af[mt][1]), "r"(af[mt][2]), "r"(af[mt][3]),
                          "r"(bf[nt][0]), "r"(bf[nt][1]));
        }
    }

    // -------- staged epilogue: acc -> smem bf16 -> coalesced STG.128 --------
    __syncthreads();   // all warps done reading stages; safe to reuse smem
    #pragma unroll
    for (int mt = 0; mt < 4; mt++) {
        int r = warpM * 64 + mt * 16 + (lane >> 2);
        #pragma unroll
        for (int nt = 0; nt < 4; nt++) {
            int c = warpN * 32 + nt * 8 + (lane & 3) * 2;
            *(__nv_bfloat162*)(smem + r * ESTRIDE + c * 2) =
                __floats2bfloat162_rn(acc[mt][nt][0], acc[mt][nt][1]);
            *(__nv_bfloat162*)(smem + (r + 8) * ESTRIDE + c * 2) =
                __floats2bfloat162_rn(acc[mt][nt][2], acc[mt][nt][3]);
        }
    }
    __syncthreads();
    {
        const int row  = tid >> 1;
        const int half = tid & 1;
        const uint4* src = (const uint4*)(smem + row * ESTRIDE + half * 128);
        uint4* dst = (uint4*)(C + (bm + row) * HDIM + bn + half * 64);
        #pragma unroll
        for (int i = 0; i < 8; i++) dst[i] = src[i];
    }
}

// ---------------- fp32 -> bf16 convert ----------------
__global__ __launch_bounds__(256) void cvt_k(const float* __restrict__ in,
                                             __nv_bfloat16* __restrict__ out)
{
    size_t i = ((size_t)blockIdx.x * blockDim.x + threadIdx.x) * 8;
    float4 a = *(const float4*)(in + i);
    float4 b = *(const float4*)(in + i + 4);
    __nv_bfloat162 r[4];
    r[0] = __floats2bfloat162_rn(a.x, a.y);
    r[1] = __floats2bfloat162_rn(a.z, a.w);
    r[2] = __floats2bfloat162_rn(b.x, b.y);
    r[3] = __floats2bfloat162_rn(b.z, b.w);
    *(uint4*)(out + i) = *(const uint4*)r;
}

// ---------------- transpose + convert ----------------
__global__ __launch_bounds__(256) void cvtT_k(const float* __restrict__ W,
                                              __nv_bfloat16* __restrict__ Wt)
{
    __shared__ float t[32][33];
    int x  = blockIdx.x * 32 + threadIdx.x;
    int y0 = blockIdx.y * 32;
    #pragma unroll
    for (int r = threadIdx.y; r < 32; r += 8)
        t[r][threadIdx.x] = W[(size_t)(y0 + r) * HDIM + x];
    __syncthreads();
    int xo = y0 + threadIdx.x;
    #pragma unroll
    for (int r = threadIdx.y; r < 32; r += 8)
        Wt[(size_t)(blockIdx.x * 32 + r) * HDIM + xo] = __float2bfloat16(t[threadIdx.x][r]);
}

// ---------------- fused: q-LN + keyp-LN + relu(q+keyp).Wb -> beta ----------------
__global__ __launch_bounds__(256) void beta_k(
    const __nv_bfloat16* __restrict__ kc, const __nv_bfloat16* __restrict__ qpre,
    const float* __restrict__ bq, const float* __restrict__ gq,
    const float* __restrict__ betaq,
    const float* __restrict__ bk, const float* __restrict__ gk,
    const float* __restrict__ betak, const float* __restrict__ Wb,
    const float* __restrict__ bb, float* __restrict__ beta)
{
    __shared__ float bks[HDIM], gks[HDIM], cqs[HDIM], wbs[HDIM];
    __shared__ float red[16];
    extern __shared__ __align__(16) __nv_bfloat16 rowbuf[];

    const int b    = blockIdx.x;
    const int tid  = threadIdx.x;
    const int lane = tid & 31;
    const int wid  = tid >> 5;

    // --- shared preload + q-row LayerNorm ---
    float xq[4];
    {
        for (int j = tid; j < HDIM; j += 256) {
            bks[j] = bk[j];
            gks[j] = gk[j];
            wbs[j] = Wb[j];
        }
        const int j0 = tid * 4;
        uint2 raw = *(const uint2*)(qpre + (size_t)b * HDIM + j0);
        const __nv_bfloat162* v2 = (const __nv_bfloat162*)&raw;
        float ls = 0.f, lq = 0.f;
        #pragma unroll
        for (int e = 0; e < 2; e++) {
            xq[2*e]   = __low2float(v2[e])  + bq[j0 + 2*e];
            xq[2*e+1] = __high2float(v2[e]) + bq[j0 + 2*e + 1];
        }
        #pragma unroll
        for (int e = 0; e < 4; e++) { ls += xq[e]; lq += xq[e] * xq[e]; }
        #pragma unroll
        for (int o = 16; o > 0; o >>= 1) {
            ls += __shfl_xor_sync(0xffffffffu, ls, o);
            lq += __shfl_xor_sync(0xffffffffu, lq, o);
        }
        if (lane == 0) { red[wid] = ls; red[wid + 8] = lq; }
        __syncthreads();
        float ts = 0.f, tq = 0.f;
        #pragma unroll
        for (int w = 0; w < 8; w++) { ts += red[w]; tq += red[w + 8]; }
        float mean = ts * (1.f / 1024.f);
        float var  = tq * (1.f / 1024.f) - mean * mean;
        float rstd = rsqrtf(var + 1e-5f);
        #pragma unroll
        for (int e = 0; e < 4; e++) {
            int j = j0 + e;
            cqs[j] = (xq[e] - mean) * rstd * gq[j] + betaq[j] + betak[j];
        }
    }
    __syncthreads();
    const float bbv = bb[0];

    __nv_bfloat16* mybuf = rowbuf + wid * 2 * HDIM;
    const uint32_t buf_s = smem_u32(mybuf);
    const __nv_bfloat16* gbase = kc + ((size_t)b * SDIM) * HDIM;

    {
        const __nv_bfloat16* src = gbase + (size_t)wid * HDIM;
        #pragma unroll
        for (int qd = 0; qd < 4; qd++)
            CPASYNC16(buf_s + qd * 512 + lane * 16, src + qd * 256 + lane * 8);
        CP_COMMIT();
    }

    #pragma unroll
    for (int i = 0; i < 8; i++) {
        const int s = wid + i * 8;
        if (i < 7) {
            const __nv_bfloat16* src = gbase + (size_t)(s + 8) * HDIM;
            const uint32_t d = buf_s + ((i + 1) & 1) * (HDIM * 2);
            #pragma unroll
            for (int qd = 0; qd < 4; qd++)
                CPASYNC16(d + qd * 512 + lane * 16, src + qd * 256 + lane * 8);
            CP_COMMIT();
            CP_WAIT1();
        } else {
            CP_WAIT0();
        }
        __syncwarp();

        const __nv_bfloat16* rb = mybuf + (i & 1) * HDIM;
        float x[32];
        float sm = 0.f, sq = 0.f;
        #pragma unroll
        for (int it = 0; it < 4; it++) {
            int j0 = it * 256 + lane * 8;
            uint4 raw = *(const uint4*)(rb + j0);
            const __nv_bfloat162* v2 = (const __nv_bfloat162*)&raw;
            #pragma unroll
            for (int e = 0; e < 4; e++) {
                float a = __low2float(v2[e])  + bks[j0 + 2*e];
                float c = __high2float(v2[e]) + bks[j0 + 2*e + 1];
                x[it*8 + 2*e]     = a;
                x[it*8 + 2*e + 1] = c;
                sm += a + c; sq += a * a + c * c;
            }
        }
        __syncwarp();
        #pragma unroll
        for (int o = 16; o > 0; o >>= 1) {
            sm += __shfl_xor_sync(0xffffffffu, sm, o);
            sq += __shfl_xor_sync(0xffffffffu, sq, o);
        }
        float mean = sm * (1.f / 1024.f);
        float var  = sq * (1.f / 1024.f) - mean * mean;
        float rstd = rsqrtf(var + 1e-5f);

        float acc = 0.f;
        #pragma unroll
        for (int it = 0; it < 4; it++) {
            int j0 = it * 256 + lane * 8;
            #pragma unroll
            for (int e = 0; e < 8; e++) {
                float hv = (x[it*8 + e] - mean) * rstd * gks[j0 + e] + cqs[j0 + e];
                acc += fmaxf(hv, 0.f) * wbs[j0 + e];
            }
        }
        #pragma unroll
        for (int o = 16; o > 0; o >>= 1)
            acc += __shfl_xor_sync(0xffffffffu, acc, o);

        if (lane == 0)
            beta[(size_t)b * SDIM + s] = (acc + bbv) * (1.f / 32.f);
    }
}
#define BETA_DYN_SMEM (8 * 2 * HDIM * 2)   // 32768 B

// ---------------- masked softmax + cumsums ----------------
__global__ void softmax_k(const float* __restrict__ beta,
                          const float* __restrict__ prev_p,
                          float* __restrict__ out)
{
    int b = blockIdx.x * blockDim.x + threadIdx.x;
    if (b >= BDIM) return;
    const float* bt = beta   + (size_t)b * SDIM;
    const float* pp = prev_p + (size_t)b * SDIM;

    float mx = -1e30f;
    #pragma unroll
    for (int s = 0; s < SDIM; s++) mx = fmaxf(mx, bt[s]);

    float pcs[SDIM];
    float run = 0.f;
    #pragma unroll
    for (int s = 0; s < SDIM; s++) { run += pp[s]; pcs[s] = run; }

    float x[SDIM];
    float denom = 0.f;
    #pragma unroll
    for (int s = 0; s < SDIM; s++) {
        float mask = (s < SDIM - 1)
                   ? ((pcs[s + 1] < 1e-5f) ? 0.f : pcs[s + 1])
                   : 1.f;
        x[s] = expf(bt[s] - mx) * mask;
        denom += fabsf(x[s]);
    }
    denom = fmaxf(denom, 1e-12f);

    const size_t BS = (size_t)BDIM * SDIM;
    float cp = 0.f;
    #pragma unroll
    for (int s = 0; s < SDIM; s++) {
        float p = x[s] / denom;
        x[s] = p;
        cp += p;
        out[0 * BS + (size_t)b * SDIM + s] = cp;
        out[2 * BS + (size_t)b * SDIM + s] = p;
    }
    float rcp = 0.f;
    #pragma unroll
    for (int s = SDIM - 1; s >= 0; s--) {
        rcp += x[s];
        out[1 * BS + (size_t)b * SDIM + s] = rcp;
    }
}

// ---------------- launch ----------------
extern "C" void kernel_launch(void* const* d_in, const int* in_sizes, int n_in,
                              void* d_out, int out_size)
{
    const float* in_val     = (const float*)d_in[0];
    const float* prev_out_M = (const float*)d_in[1];
    const float* prev_p     = (const float*)d_in[2];
    const float* Wq         = (const float*)d_in[3];
    const float* bq         = (const float*)d_in[4];
    const float* gq         = (const float*)d_in[5];
    const float* betaq      = (const float*)d_in[6];
    const float* Wk         = (const float*)d_in[7];
    const float* bk         = (const float*)d_in[8];
    const float* gk         = (const float*)d_in[9];
    const float* betak      = (const float*)d_in[10];
    const float* Wb         = (const float*)d_in[11];
    const float* bb         = (const float*)d_in[12];
    float* out = (float*)d_out;

    __nv_bfloat16 *abf, *inbf, *wqt, *wkt, *kc, *qpre;
    float *betap;
    cudaGetSymbolAddress((void**)&abf,   g_abf);
    cudaGetSymbolAddress((void**)&inbf,  g_inbf);
    cudaGetSymbolAddress((void**)&wqt,   g_wqt);
    cudaGetSymbolAddress((void**)&wkt,   g_wkt);
    cudaGetSymbolAddress((void**)&kc,    g_kc);
    cudaGetSymbolAddress((void**)&qpre,  g_qpre);
    cudaGetSymbolAddress((void**)&betap, g_beta);

    cudaFuncSetAttribute(gemm_bf16_k, cudaFuncAttributeMaxDynamicSharedMemorySize, GEMM_SMEM);
    cudaFuncSetAttribute(beta_k, cudaFuncAttributeMaxDynamicSharedMemorySize, BETA_DYN_SMEM);

    cvt_k <<<((size_t)MROWS * HDIM / 8) / 256, 256>>>(prev_out_M, abf);
    cvt_k <<<((size_t)BDIM  * HDIM / 8) / 256, 256>>>(in_val, inbf);
    cvtT_k<<<dim3(32, 32), dim3(32, 8)>>>(Wq, wqt);
    cvtT_k<<<dim3(32, 32), dim3(32, 8)>>>(Wk, wkt);

    // merged GEMM: y<16 -> query GEMM, else key GEMM
    gemm_bf16_k<<<dim3(8, QBLKS + MROWS / 128), 256, GEMM_SMEM>>>(
        inbf, wqt, qpre, abf, wkt, kc);

    beta_k<<<BDIM, 256, BETA_DYN_SMEM>>>(
        kc, qpre, bq, gq, betaq, bk, gk, betak, Wb, bb, betap);
    softmax_k<<<(BDIM + 127) / 128, 128>>>(betap, prev_p, out);
}